// round 15
// baseline (speedup 1.0000x reference)
#include <cuda_runtime.h>
#include <math.h>

#define N_RES  8192
#define N_IN   128
#define BATCH  16
#define LEAK   0.9f

#define NCB     256                 // coarse bins (32 rows each)
#define CCAP    28672               // per-bin capacity
#define DEPTH_C 64                  // coarse staging depth (R11 proven)
#define NCH     152                 // coarse stream chunks (1/SM, R11 proven)
#define TC      8192                // entries per coarse round (1024 thr x 8)

#define NSEG    2                   // fuse segments per bin (grid = 512)
#define DEPTH_F 192                 // fuse staging depth per row per round
#define TF      4096                // entries per fuse round (512 thr x 8)

#define COARSE_SMEM (NCB * DEPTH_C * (int)sizeof(float2))   // 128 KB
#define FUSE_SMEM   (32 * DEPTH_F * (int)sizeof(float2))    // 48 KB

// ---------------------------------------------------------------------------
// Scratch (allocation-free __device__ globals)
__device__ __align__(16) float g_z[N_RES * BATCH];          // bias + input + reservoir acc
__device__ __align__(16) float g_state_T[N_RES * BATCH];    // [row][batch]
__device__ __align__(16) float g_x_T[N_IN * BATCH];
__device__ unsigned g_ccur[NCB];
__device__ unsigned g_done[NCB];
__device__ __align__(16) float2 g_cbucket[(size_t)NCB * CCAP];  // 58.7 MB

__device__ __forceinline__ void red_add_v4(float* p, float a, float b, float c, float d) {
    asm volatile("red.global.add.v4.f32 [%0], {%1,%2,%3,%4};"
                 :: "l"(p), "f"(a), "f"(b), "f"(c), "f"(d) : "memory");
}
__device__ __forceinline__ void red_add_f32(float* p, float a) {
    asm volatile("red.global.add.f32 [%0], %1;" :: "l"(p), "f"(a) : "memory");
}

// ---------------------------------------------------------------------------
// Kernel 1: init z with biases, zero cursors/counters, transpose state and x.
__global__ void k_init(const float* __restrict__ state,
                       const float* __restrict__ x,
                       const float* __restrict__ res_bias,
                       const float* __restrict__ in_bias) {
    int i = blockIdx.x * blockDim.x + threadIdx.x;
    if (i < N_RES * BATCH) {
        int r = i >> 4;
        int b = i & (BATCH - 1);
        g_z[i]       = res_bias[r] + in_bias[r];
        g_state_T[i] = state[b * N_RES + r];
    }
    if (i < N_IN * BATCH) {
        int r = i >> 4;
        int b = i & (BATCH - 1);
        g_x_T[i] = x[b * N_IN + r];
    }
    if (i < NCB) { g_ccur[i] = 0; g_done[i] = 0; }
}

// ---------------------------------------------------------------------------
// Kernel 2: input SpMM (small: ~105K entries).
__global__ void k_in_spmm(const float* __restrict__ vals,
                          const int*   __restrict__ rows,
                          const int*   __restrict__ cols,
                          int nnz) {
    int i = blockIdx.x * blockDim.x + threadIdx.x;
    if (i >= nnz) return;
    float v = vals[i];
    int r = rows[i];
    int c = cols[i];
    const float4* s = reinterpret_cast<const float4*>(g_x_T + c * BATCH);
    float4 s0 = s[0], s1 = s[1], s2 = s[2], s3 = s[3];
    float* zp = g_z + r * BATCH;
    red_add_v4(zp + 0,  v * s0.x, v * s0.y, v * s0.z, v * s0.w);
    red_add_v4(zp + 4,  v * s1.x, v * s1.y, v * s1.z, v * s1.w);
    red_add_v4(zp + 8,  v * s2.x, v * s2.y, v * s2.z, v * s2.w);
    red_add_v4(zp + 12, v * s3.x, v * s3.y, v * s3.z, v * s3.w);
}

// ---------------------------------------------------------------------------
// Kernel 3: coarse partition by row-block (r>>5) — R11's proven version.
__global__ void __launch_bounds__(1024) k_coarse(const float* __restrict__ vals,
                                                 const int*   __restrict__ rows,
                                                 const int*   __restrict__ cols,
                                                 int nnz, int csz) {
    extern __shared__ float2 sbuf[];             // NCB * DEPTH_C
    __shared__ unsigned scnt[NCB];
    __shared__ unsigned sbase[NCB];
    int tid  = threadIdx.x;
    int w    = tid >> 5;
    int lane = tid & 31;
    int start = blockIdx.x * csz;
    int end   = min(nnz, start + csz);

    for (int base = start; base < end; base += TC) {
        if (tid < NCB) scnt[tid] = 0;
        __syncthreads();

        int i0 = base + tid * 8;
        if (base + TC <= end) {
            float4 v0 = *(const float4*)(vals + i0);
            float4 v1 = *(const float4*)(vals + i0 + 4);
            int4   r0 = *(const int4*)(rows + i0);
            int4   r1 = *(const int4*)(rows + i0 + 4);
            int4   c0 = *(const int4*)(cols + i0);
            int4   c1 = *(const int4*)(cols + i0 + 4);
            float vv[8] = {v0.x, v0.y, v0.z, v0.w, v1.x, v1.y, v1.z, v1.w};
            int   rr[8] = {r0.x, r0.y, r0.z, r0.w, r1.x, r1.y, r1.z, r1.w};
            int   cc[8] = {c0.x, c0.y, c0.z, c0.w, c1.x, c1.y, c1.z, c1.w};
#pragma unroll
            for (int k = 0; k < 8; k++) {
                int bin = rr[k] >> 5;
                unsigned pos = atomicAdd(&scnt[bin], 1u);
                float2 e = make_float2(vv[k],
                    __int_as_float(cc[k] | ((rr[k] & 31) << 13)));
                if (pos < DEPTH_C) sbuf[bin * DEPTH_C + pos] = e;
                else {                                   // ~never
                    unsigned p = atomicAdd(&g_ccur[bin], 1u);
                    if (p < CCAP) g_cbucket[(size_t)bin * CCAP + p] = e;
                }
            }
        } else {
            for (int k = 0; k < 8; k++) {
                int i = i0 + k;
                if (i < end) {
                    int r = rows[i], c = cols[i];
                    int bin = r >> 5;
                    unsigned pos = atomicAdd(&scnt[bin], 1u);
                    float2 e = make_float2(vals[i],
                        __int_as_float(c | ((r & 31) << 13)));
                    if (pos < DEPTH_C) sbuf[bin * DEPTH_C + pos] = e;
                    else {
                        unsigned p = atomicAdd(&g_ccur[bin], 1u);
                        if (p < CCAP) g_cbucket[(size_t)bin * CCAP + p] = e;
                    }
                }
            }
        }
        __syncthreads();

        if (tid < NCB) {
            unsigned c = min(scnt[tid], (unsigned)DEPTH_C);
            sbase[tid] = c ? atomicAdd(&g_ccur[tid], c) : 0u;
        }
        __syncthreads();

        for (int b = w * 8; b < w * 8 + 8; b++) {
            unsigned cnt = min(scnt[b], (unsigned)DEPTH_C);
            if (cnt == 0) continue;
            size_t dst = (size_t)b * CCAP + sbase[b];
            if (lane < cnt)
                g_cbucket[dst + lane] = sbuf[b * DEPTH_C + lane];
            if (cnt > 32 && lane + 32 < cnt)
                g_cbucket[dst + lane + 32] = sbuf[b * DEPTH_C + lane + 32];
        }
        __syncthreads();
    }
}

// ---------------------------------------------------------------------------
// Slow path for staging overflow (exact, ~never taken).
__device__ __forceinline__ void stage_overflow(float2 e, int cb, int rl) {
    int c = __float_as_int(e.y) & 8191;
    float v = e.x;
    const float4* s4 = reinterpret_cast<const float4*>(g_state_T + c * BATCH);
    float4 s0 = s4[0], s1 = s4[1], s2 = s4[2], s3 = s4[3];
    float* zp = g_z + ((cb << 5) | rl) * BATCH;
    red_add_v4(zp + 0,  v * s0.x, v * s0.y, v * s0.z, v * s0.w);
    red_add_v4(zp + 4,  v * s1.x, v * s1.y, v * s1.z, v * s1.w);
    red_add_v4(zp + 8,  v * s2.x, v * s2.y, v * s2.z, v * s2.w);
    red_add_v4(zp + 12, v * s3.x, v * s3.y, v * s3.z, v * s3.w);
}

// ---------------------------------------------------------------------------
// Kernel 4 (ncu slot): fused refine + gather + epilogue.
// Staging: warp-aggregated counter atomics with WARP-UNIFORM loop bounds
// (k0 is identical across the warp; __match_any_sync always sees 32 lanes).
__global__ void __launch_bounds__(512, 4) k_fuse(float* __restrict__ out) {
    extern __shared__ float2 stg[];              // 32 * DEPTH_F
    __shared__ unsigned scnt[32];
    __shared__ unsigned sdone;
    int tid  = threadIdx.x;
    int w    = tid >> 5;
    int lane = tid & 31;
    int half = lane >> 4;
    int b    = lane & 15;
    int cb   = blockIdx.x >> 1;
    int seg  = blockIdx.x & 1;
    unsigned lt_mask = (1u << lane) - 1u;

    int cnt = min(g_ccur[cb], (unsigned)CCAP);
    int s_beg = seg ? (cnt >> 1) : 0;
    int s_end = seg ? cnt : (cnt >> 1);
    const float2* __restrict__ src = g_cbucket + (size_t)cb * CCAP;

    float acc0 = 0.0f, acc1 = 0.0f;              // rows cb*32+2w, +2w+1

    for (int base = s_beg; base < s_end; base += TF) {
        if (tid < 32) scnt[tid] = 0;
        __syncthreads();

        int n = min(TF, s_end - base);

        // Full-warp chunks: bound depends only on warp-uniform k0.
        int k0 = w << 5;
        for (; k0 + 32 <= n; k0 += 512) {
            float2 e = src[base + k0 + lane];
            int rl = (__float_as_int(e.y) >> 13) & 31;
            unsigned mask = __match_any_sync(0xffffffffu, rl);
            int leader = __ffs(mask) - 1;
            unsigned posb = 0;
            if (lane == leader) posb = atomicAdd(&scnt[rl], (unsigned)__popc(mask));
            posb = __shfl_sync(0xffffffffu, posb, leader);
            unsigned pos = posb + __popc(mask & lt_mask);
            if (pos < DEPTH_F) stg[rl * DEPTH_F + pos] = e;
            else               stage_overflow(e, cb, rl);
        }
        // At most one partial chunk per warp: plain per-thread atomics.
        if (k0 < n) {
            int k = k0 + lane;
            if (k < n) {
                float2 e = src[base + k];
                int rl = (__float_as_int(e.y) >> 13) & 31;
                unsigned pos = atomicAdd(&scnt[rl], 1u);
                if (pos < DEPTH_F) stg[rl * DEPTH_F + pos] = e;
                else               stage_overflow(e, cb, rl);
            }
        }
        __syncthreads();

        // Drain: warp w -> rows 2w, 2w+1; half-warp = one entry; 8 in flight.
#pragma unroll
        for (int rr = 0; rr < 2; rr++) {
            int rl = (w << 1) | rr;
            int m = min(scnt[rl], (unsigned)DEPTH_F);
            const float2* row = stg + rl * DEPTH_F;
            float acc = 0.0f;
            int j = half;
            for (; j + 14 < m; j += 16) {
                float2 e0 = row[j];
                float2 e1 = row[j + 2];
                float2 e2 = row[j + 4];
                float2 e3 = row[j + 6];
                float2 e4 = row[j + 8];
                float2 e5 = row[j + 10];
                float2 e6 = row[j + 12];
                float2 e7 = row[j + 14];
                float s0 = g_state_T[(__float_as_int(e0.y) & 8191) * BATCH + b];
                float s1 = g_state_T[(__float_as_int(e1.y) & 8191) * BATCH + b];
                float s2 = g_state_T[(__float_as_int(e2.y) & 8191) * BATCH + b];
                float s3 = g_state_T[(__float_as_int(e3.y) & 8191) * BATCH + b];
                float s4 = g_state_T[(__float_as_int(e4.y) & 8191) * BATCH + b];
                float s5 = g_state_T[(__float_as_int(e5.y) & 8191) * BATCH + b];
                float s6 = g_state_T[(__float_as_int(e6.y) & 8191) * BATCH + b];
                float s7 = g_state_T[(__float_as_int(e7.y) & 8191) * BATCH + b];
                acc = fmaf(e0.x, s0, acc);
                acc = fmaf(e1.x, s1, acc);
                acc = fmaf(e2.x, s2, acc);
                acc = fmaf(e3.x, s3, acc);
                acc = fmaf(e4.x, s4, acc);
                acc = fmaf(e5.x, s5, acc);
                acc = fmaf(e6.x, s6, acc);
                acc = fmaf(e7.x, s7, acc);
            }
            for (; j < m; j += 2) {
                float2 e = row[j];
                acc = fmaf(e.x, g_state_T[(__float_as_int(e.y) & 8191) * BATCH + b], acc);
            }
            if (rr) acc1 += acc; else acc0 += acc;
        }
        __syncthreads();
    }

    // Flush 32-row partials into g_z.
    acc0 += __shfl_xor_sync(0xffffffffu, acc0, 16);
    acc1 += __shfl_xor_sync(0xffffffffu, acc1, 16);
    if (lane < BATCH) {
        int r0 = (cb << 5) | (w << 1);
        red_add_f32(g_z + r0 * BATCH + lane, acc0);
        red_add_f32(g_z + (r0 + 1) * BATCH + lane, acc1);
    }
    __syncthreads();

    // Completion counter: last segment-block of the bin runs the epilogue.
    if (tid == 0) {
        __threadfence();
        sdone = atomicAdd(&g_done[cb], 1u);
    }
    __syncthreads();
    if (sdone == NSEG - 1) {
        __threadfence();
        int i = (cb << 9) | tid;                 // bin's 512 outputs (32 rows x 16)
        float z = g_z[i];
        float s = g_state_T[i];                  // = state[b][r]
        int r = i >> 4;
        int bb = i & 15;
        out[bb * N_RES + r] = (1.0f - LEAK) * s + LEAK * erff(z);
    }
}

// ---------------------------------------------------------------------------
extern "C" void kernel_launch(void* const* d_in, const int* in_sizes, int n_in,
                              void* d_out, int out_size) {
    const float* state    = (const float*)d_in[0];
    const float* x        = (const float*)d_in[1];
    const float* res_vals = (const float*)d_in[2];
    const int*   res_rows = (const int*)  d_in[3];
    const int*   res_cols = (const int*)  d_in[4];
    const float* res_bias = (const float*)d_in[5];
    const float* in_vals  = (const float*)d_in[6];
    const int*   in_rows  = (const int*)  d_in[7];
    const int*   in_cols  = (const int*)  d_in[8];
    const float* in_bias  = (const float*)d_in[9];
    float* out = (float*)d_out;

    int res_nnz = in_sizes[2];
    int in_nnz  = in_sizes[6];
    int csz = ((res_nnz + NCH - 1) / NCH + 7) & ~7;

    static int smem_set = 0;
    if (!smem_set) {
        cudaFuncSetAttribute(k_coarse, cudaFuncAttributeMaxDynamicSharedMemorySize, COARSE_SMEM);
        cudaFuncSetAttribute(k_fuse,   cudaFuncAttributeMaxDynamicSharedMemorySize, FUSE_SMEM);
        smem_set = 1;
    }

    // Launch order: slot 4 (ncu capture) = k_fuse.
    k_init<<<(N_RES * BATCH + 255) / 256, 256>>>(state, x, res_bias, in_bias);

    k_in_spmm<<<(in_nnz + 255) / 256, 256>>>(in_vals, in_rows, in_cols, in_nnz);

    k_coarse<<<NCH, 1024, COARSE_SMEM>>>(res_vals, res_rows, res_cols, res_nnz, csz);

    k_fuse<<<NCB * NSEG, 512, FUSE_SMEM>>>(out);
}

// round 16
// speedup vs baseline: 1.0325x; 1.0325x over previous
#include <cuda_runtime.h>
#include <math.h>

#define N_RES  8192
#define N_IN   128
#define BATCH  16
#define LEAK   0.9f

#define NCB     256                 // coarse bins (32 rows each)
#define CCAP    28672               // per-bin capacity
#define DEPTH_C 64                  // coarse staging depth (R11 proven)
#define NCH     152                 // coarse stream chunks (1/SM, R11 proven)
#define TC      8192                // entries per coarse round (1024 thr x 8)

#define NSEG    2                   // fuse segments per bin (grid = 512)
#define DEPTH_F 192                 // fuse staging depth per row per round
#define TF      4096                // entries per fuse round (512 thr x 8)

#define COARSE_SMEM (NCB * DEPTH_C * (int)sizeof(float2))   // 128 KB
#define FUSE_SMEM   (32 * DEPTH_F * (int)sizeof(float2))    // 48 KB

// ---------------------------------------------------------------------------
// Scratch (allocation-free __device__ globals)
__device__ __align__(16) float g_z[N_RES * BATCH];          // bias + input + reservoir acc
__device__ __align__(16) float g_state_T[N_RES * BATCH];    // [row][batch]
__device__ __align__(16) float g_x_T[N_IN * BATCH];
__device__ unsigned g_ccur[NCB];
__device__ unsigned g_done[NCB];
__device__ __align__(16) float2 g_cbucket[(size_t)NCB * CCAP];  // 58.7 MB

__device__ __forceinline__ void red_add_v4(float* p, float a, float b, float c, float d) {
    asm volatile("red.global.add.v4.f32 [%0], {%1,%2,%3,%4};"
                 :: "l"(p), "f"(a), "f"(b), "f"(c), "f"(d) : "memory");
}

// ---------------------------------------------------------------------------
// Kernel 1: init z with biases, zero cursors/counters, transpose state and x.
__global__ void k_init(const float* __restrict__ state,
                       const float* __restrict__ x,
                       const float* __restrict__ res_bias,
                       const float* __restrict__ in_bias) {
    int i = blockIdx.x * blockDim.x + threadIdx.x;
    if (i < N_RES * BATCH) {
        int r = i >> 4;
        int b = i & (BATCH - 1);
        g_z[i]       = res_bias[r] + in_bias[r];
        g_state_T[i] = state[b * N_RES + r];
    }
    if (i < N_IN * BATCH) {
        int r = i >> 4;
        int b = i & (BATCH - 1);
        g_x_T[i] = x[b * N_IN + r];
    }
    if (i < NCB) { g_ccur[i] = 0; g_done[i] = 0; }
}

// ---------------------------------------------------------------------------
// Kernel 2: input SpMM (small: ~105K entries).
__global__ void k_in_spmm(const float* __restrict__ vals,
                          const int*   __restrict__ rows,
                          const int*   __restrict__ cols,
                          int nnz) {
    int i = blockIdx.x * blockDim.x + threadIdx.x;
    if (i >= nnz) return;
    float v = vals[i];
    int r = rows[i];
    int c = cols[i];
    const float4* s = reinterpret_cast<const float4*>(g_x_T + c * BATCH);
    float4 s0 = s[0], s1 = s[1], s2 = s[2], s3 = s[3];
    float* zp = g_z + r * BATCH;
    red_add_v4(zp + 0,  v * s0.x, v * s0.y, v * s0.z, v * s0.w);
    red_add_v4(zp + 4,  v * s1.x, v * s1.y, v * s1.z, v * s1.w);
    red_add_v4(zp + 8,  v * s2.x, v * s2.y, v * s2.z, v * s2.w);
    red_add_v4(zp + 12, v * s3.x, v * s3.y, v * s3.z, v * s3.w);
}

// ---------------------------------------------------------------------------
// Kernel 3: coarse partition by row-block (r>>5) — R11's proven version.
__global__ void __launch_bounds__(1024) k_coarse(const float* __restrict__ vals,
                                                 const int*   __restrict__ rows,
                                                 const int*   __restrict__ cols,
                                                 int nnz, int csz) {
    extern __shared__ float2 sbuf[];             // NCB * DEPTH_C
    __shared__ unsigned scnt[NCB];
    __shared__ unsigned sbase[NCB];
    int tid  = threadIdx.x;
    int w    = tid >> 5;
    int lane = tid & 31;
    int start = blockIdx.x * csz;
    int end   = min(nnz, start + csz);

    for (int base = start; base < end; base += TC) {
        if (tid < NCB) scnt[tid] = 0;
        __syncthreads();

        int i0 = base + tid * 8;
        if (base + TC <= end) {
            float4 v0 = *(const float4*)(vals + i0);
            float4 v1 = *(const float4*)(vals + i0 + 4);
            int4   r0 = *(const int4*)(rows + i0);
            int4   r1 = *(const int4*)(rows + i0 + 4);
            int4   c0 = *(const int4*)(cols + i0);
            int4   c1 = *(const int4*)(cols + i0 + 4);
            float vv[8] = {v0.x, v0.y, v0.z, v0.w, v1.x, v1.y, v1.z, v1.w};
            int   rr[8] = {r0.x, r0.y, r0.z, r0.w, r1.x, r1.y, r1.z, r1.w};
            int   cc[8] = {c0.x, c0.y, c0.z, c0.w, c1.x, c1.y, c1.z, c1.w};
#pragma unroll
            for (int k = 0; k < 8; k++) {
                int bin = rr[k] >> 5;
                unsigned pos = atomicAdd(&scnt[bin], 1u);
                float2 e = make_float2(vv[k],
                    __int_as_float(cc[k] | ((rr[k] & 31) << 13)));
                if (pos < DEPTH_C) sbuf[bin * DEPTH_C + pos] = e;
                else {                                   // ~never
                    unsigned p = atomicAdd(&g_ccur[bin], 1u);
                    if (p < CCAP) g_cbucket[(size_t)bin * CCAP + p] = e;
                }
            }
        } else {
            for (int k = 0; k < 8; k++) {
                int i = i0 + k;
                if (i < end) {
                    int r = rows[i], c = cols[i];
                    int bin = r >> 5;
                    unsigned pos = atomicAdd(&scnt[bin], 1u);
                    float2 e = make_float2(vals[i],
                        __int_as_float(c | ((r & 31) << 13)));
                    if (pos < DEPTH_C) sbuf[bin * DEPTH_C + pos] = e;
                    else {
                        unsigned p = atomicAdd(&g_ccur[bin], 1u);
                        if (p < CCAP) g_cbucket[(size_t)bin * CCAP + p] = e;
                    }
                }
            }
        }
        __syncthreads();

        if (tid < NCB) {
            unsigned c = min(scnt[tid], (unsigned)DEPTH_C);
            sbase[tid] = c ? atomicAdd(&g_ccur[tid], c) : 0u;
        }
        __syncthreads();

        for (int b = w * 8; b < w * 8 + 8; b++) {
            unsigned cnt = min(scnt[b], (unsigned)DEPTH_C);
            if (cnt == 0) continue;
            size_t dst = (size_t)b * CCAP + sbase[b];
            if (lane < cnt)
                g_cbucket[dst + lane] = sbuf[b * DEPTH_C + lane];
            if (cnt > 32 && lane + 32 < cnt)
                g_cbucket[dst + lane + 32] = sbuf[b * DEPTH_C + lane + 32];
        }
        __syncthreads();
    }
}

// ---------------------------------------------------------------------------
// Slow path for staging overflow (exact, ~never taken).
__device__ __forceinline__ void stage_overflow(float2 e, int cb, int rl) {
    int c = __float_as_int(e.y) & 8191;
    float v = e.x;
    const float4* s4 = reinterpret_cast<const float4*>(g_state_T + c * BATCH);
    float4 s0 = s4[0], s1 = s4[1], s2 = s4[2], s3 = s4[3];
    float* zp = g_z + ((cb << 5) | rl) * BATCH;
    red_add_v4(zp + 0,  v * s0.x, v * s0.y, v * s0.z, v * s0.w);
    red_add_v4(zp + 4,  v * s1.x, v * s1.y, v * s1.z, v * s1.w);
    red_add_v4(zp + 8,  v * s2.x, v * s2.y, v * s2.z, v * s2.w);
    red_add_v4(zp + 12, v * s3.x, v * s3.y, v * s3.z, v * s3.w);
}

// ---------------------------------------------------------------------------
// Kernel 4 (ncu slot): fused refine + gather + epilogue.
// Staging: plain per-thread smem atomics (R13 proven).
// Drain: quad-per-entry — 4 lanes per entry, float4 state loads.
//   quad = lane>>2 selects entry, ql = lane&3 selects batch group (4 floats).
//   Per warp-instr: LDS serves 8 entries, LDG.128 serves 8 entries.
__global__ void __launch_bounds__(512, 4) k_fuse(float* __restrict__ out) {
    extern __shared__ float2 stg[];              // 32 * DEPTH_F
    __shared__ unsigned scnt[32];
    __shared__ unsigned sdone;
    int tid  = threadIdx.x;
    int w    = tid >> 5;
    int lane = tid & 31;
    int quad = lane >> 2;                        // 0..7: entry slot
    int ql   = lane & 3;                         // batch group (4 floats)
    int cb   = blockIdx.x >> 1;
    int seg  = blockIdx.x & 1;

    int cnt = min(g_ccur[cb], (unsigned)CCAP);
    int s_beg = seg ? (cnt >> 1) : 0;
    int s_end = seg ? cnt : (cnt >> 1);
    const float2* __restrict__ src = g_cbucket + (size_t)cb * CCAP;

    float4 accA = make_float4(0.f, 0.f, 0.f, 0.f);   // row 2w
    float4 accB = make_float4(0.f, 0.f, 0.f, 0.f);   // row 2w+1

    for (int base = s_beg; base < s_end; base += TF) {
        if (tid < 32) scnt[tid] = 0;
        __syncthreads();

        int n = min(TF, s_end - base);
        // Stage: all 512 threads, plain per-thread smem atomics (proven).
        for (int k = tid; k < n; k += 512) {
            float2 e = src[base + k];
            int rl = (__float_as_int(e.y) >> 13) & 31;
            unsigned pos = atomicAdd(&scnt[rl], 1u);
            if (pos < DEPTH_F) stg[rl * DEPTH_F + pos] = e;
            else               stage_overflow(e, cb, rl);
        }
        __syncthreads();

        // Drain: warp w -> rows 2w, 2w+1; quad-per-entry, float4 state loads.
#pragma unroll
        for (int rr = 0; rr < 2; rr++) {
            int rl = (w << 1) | rr;
            int m = min(scnt[rl], (unsigned)DEPTH_F);
            const float2* row = stg + rl * DEPTH_F;
            float4 acc = make_float4(0.f, 0.f, 0.f, 0.f);
            int j = 0;
            for (; j + 16 <= m; j += 16) {       // 16 entries: 2 LDS + 2 LDG.128
                float2 e0 = row[j + quad];
                float2 e1 = row[j + 8 + quad];
                float4 s0 = *reinterpret_cast<const float4*>(
                    g_state_T + (__float_as_int(e0.y) & 8191) * BATCH + (ql << 2));
                float4 s1 = *reinterpret_cast<const float4*>(
                    g_state_T + (__float_as_int(e1.y) & 8191) * BATCH + (ql << 2));
                acc.x = fmaf(e0.x, s0.x, acc.x);
                acc.y = fmaf(e0.x, s0.y, acc.y);
                acc.z = fmaf(e0.x, s0.z, acc.z);
                acc.w = fmaf(e0.x, s0.w, acc.w);
                acc.x = fmaf(e1.x, s1.x, acc.x);
                acc.y = fmaf(e1.x, s1.y, acc.y);
                acc.z = fmaf(e1.x, s1.z, acc.z);
                acc.w = fmaf(e1.x, s1.w, acc.w);
            }
            for (; j < m; j += 8) {              // guarded tail
                if (j + quad < m) {
                    float2 e = row[j + quad];
                    float4 s = *reinterpret_cast<const float4*>(
                        g_state_T + (__float_as_int(e.y) & 8191) * BATCH + (ql << 2));
                    acc.x = fmaf(e.x, s.x, acc.x);
                    acc.y = fmaf(e.x, s.y, acc.y);
                    acc.z = fmaf(e.x, s.z, acc.z);
                    acc.w = fmaf(e.x, s.w, acc.w);
                }
            }
            if (rr) { accB.x += acc.x; accB.y += acc.y; accB.z += acc.z; accB.w += acc.w; }
            else    { accA.x += acc.x; accA.y += acc.y; accA.z += acc.z; accA.w += acc.w; }
        }
        __syncthreads();
    }

    // Cross-quad reduction (lanes differing in bits 2,3,4 share the same ql).
#pragma unroll
    for (int off = 4; off < 32; off <<= 1) {
        accA.x += __shfl_xor_sync(0xffffffffu, accA.x, off);
        accA.y += __shfl_xor_sync(0xffffffffu, accA.y, off);
        accA.z += __shfl_xor_sync(0xffffffffu, accA.z, off);
        accA.w += __shfl_xor_sync(0xffffffffu, accA.w, off);
        accB.x += __shfl_xor_sync(0xffffffffu, accB.x, off);
        accB.y += __shfl_xor_sync(0xffffffffu, accB.y, off);
        accB.z += __shfl_xor_sync(0xffffffffu, accB.z, off);
        accB.w += __shfl_xor_sync(0xffffffffu, accB.w, off);
    }
    // Flush: lanes 0-3 flush row 2w (batch groups 0-3), lanes 4-7 flush row 2w+1.
    if (lane < 4) {
        int r0 = (cb << 5) | (w << 1);
        red_add_v4(g_z + r0 * BATCH + (lane << 2), accA.x, accA.y, accA.z, accA.w);
    } else if (lane < 8) {
        int r1 = ((cb << 5) | (w << 1)) + 1;
        red_add_v4(g_z + r1 * BATCH + ((lane & 3) << 2), accB.x, accB.y, accB.z, accB.w);
    }
    __syncthreads();

    // Completion counter: last segment-block of the bin runs the epilogue.
    if (tid == 0) {
        __threadfence();
        sdone = atomicAdd(&g_done[cb], 1u);
    }
    __syncthreads();
    if (sdone == NSEG - 1) {
        __threadfence();
        int i = (cb << 9) | tid;                 // bin's 512 outputs (32 rows x 16)
        float z = g_z[i];
        float s = g_state_T[i];                  // = state[b][r]
        int r = i >> 4;
        int bb = i & 15;
        out[bb * N_RES + r] = (1.0f - LEAK) * s + LEAK * erff(z);
    }
}

// ---------------------------------------------------------------------------
extern "C" void kernel_launch(void* const* d_in, const int* in_sizes, int n_in,
                              void* d_out, int out_size) {
    const float* state    = (const float*)d_in[0];
    const float* x        = (const float*)d_in[1];
    const float* res_vals = (const float*)d_in[2];
    const int*   res_rows = (const int*)  d_in[3];
    const int*   res_cols = (const int*)  d_in[4];
    const float* res_bias = (const float*)d_in[5];
    const float* in_vals  = (const float*)d_in[6];
    const int*   in_rows  = (const int*)  d_in[7];
    const int*   in_cols  = (const int*)  d_in[8];
    const float* in_bias  = (const float*)d_in[9];
    float* out = (float*)d_out;

    int res_nnz = in_sizes[2];
    int in_nnz  = in_sizes[6];
    int csz = ((res_nnz + NCH - 1) / NCH + 7) & ~7;

    static int smem_set = 0;
    if (!smem_set) {
        cudaFuncSetAttribute(k_coarse, cudaFuncAttributeMaxDynamicSharedMemorySize, COARSE_SMEM);
        cudaFuncSetAttribute(k_fuse,   cudaFuncAttributeMaxDynamicSharedMemorySize, FUSE_SMEM);
        smem_set = 1;
    }

    // Launch order: slot 4 (ncu capture) = k_fuse.
    k_init<<<(N_RES * BATCH + 255) / 256, 256>>>(state, x, res_bias, in_bias);

    k_in_spmm<<<(in_nnz + 255) / 256, 256>>>(in_vals, in_rows, in_cols, in_nnz);

    k_coarse<<<NCH, 1024, COARSE_SMEM>>>(res_vals, res_rows, res_cols, res_nnz, csz);

    k_fuse<<<NCB * NSEG, 512, FUSE_SMEM>>>(out);
}

// round 17
// speedup vs baseline: 1.1230x; 1.0877x over previous
#include <cuda_runtime.h>
#include <math.h>

#define N_RES  8192
#define N_IN   128
#define BATCH  16
#define LEAK   0.9f

#define NCB     256                 // coarse bins (32 rows each)
#define CCAP    28672               // per-bin capacity
#define DEPTH_C 64                  // coarse staging depth (R11 proven)
#define NCH     152                 // coarse stream chunks (1/SM, R11 proven)
#define TC      8192                // entries per coarse round (1024 thr x 8)

#define NSEG    2                   // fuse segments per bin (grid = 512)
#define DEPTH_F 112                 // staging depth per row (mean 64, +6 sigma)
#define TF      2048                // entries per fuse round
                                    // smem 28KB/block -> 4 blocks = 114KB -> L1D ~114KB for state

#define COARSE_SMEM (NCB * DEPTH_C * (int)sizeof(float2))   // 128 KB
#define FUSE_SMEM   (32 * DEPTH_F * (int)sizeof(float2))    // 28 KB

// ---------------------------------------------------------------------------
// Scratch (allocation-free __device__ globals)
__device__ __align__(16) float g_z[N_RES * BATCH];          // bias + input + reservoir acc
__device__ __align__(16) float g_state_T[N_RES * BATCH];    // [row][batch]
__device__ __align__(16) float g_x_T[N_IN * BATCH];
__device__ unsigned g_ccur[NCB];
__device__ unsigned g_done[NCB];
__device__ __align__(16) float2 g_cbucket[(size_t)NCB * CCAP];  // 58.7 MB

__device__ __forceinline__ void red_add_v4(float* p, float a, float b, float c, float d) {
    asm volatile("red.global.add.v4.f32 [%0], {%1,%2,%3,%4};"
                 :: "l"(p), "f"(a), "f"(b), "f"(c), "f"(d) : "memory");
}
__device__ __forceinline__ void red_add_f32(float* p, float a) {
    asm volatile("red.global.add.f32 [%0], %1;" :: "l"(p), "f"(a) : "memory");
}
__device__ __forceinline__ float2 ldcs_f2(const float2* p) {     // evict-streaming
    float2 r;
    asm volatile("ld.global.cs.v2.f32 {%0,%1}, [%2];" : "=f"(r.x), "=f"(r.y) : "l"(p));
    return r;
}

// ---------------------------------------------------------------------------
// Kernel 1: init z with biases, zero cursors/counters, transpose state and x.
__global__ void k_init(const float* __restrict__ state,
                       const float* __restrict__ x,
                       const float* __restrict__ res_bias,
                       const float* __restrict__ in_bias) {
    int i = blockIdx.x * blockDim.x + threadIdx.x;
    if (i < N_RES * BATCH) {
        int r = i >> 4;
        int b = i & (BATCH - 1);
        g_z[i]       = res_bias[r] + in_bias[r];
        g_state_T[i] = state[b * N_RES + r];
    }
    if (i < N_IN * BATCH) {
        int r = i >> 4;
        int b = i & (BATCH - 1);
        g_x_T[i] = x[b * N_IN + r];
    }
    if (i < NCB) { g_ccur[i] = 0; g_done[i] = 0; }
}

// ---------------------------------------------------------------------------
// Kernel 2: input SpMM (small: ~105K entries).
__global__ void k_in_spmm(const float* __restrict__ vals,
                          const int*   __restrict__ rows,
                          const int*   __restrict__ cols,
                          int nnz) {
    int i = blockIdx.x * blockDim.x + threadIdx.x;
    if (i >= nnz) return;
    float v = vals[i];
    int r = rows[i];
    int c = cols[i];
    const float4* s = reinterpret_cast<const float4*>(g_x_T + c * BATCH);
    float4 s0 = s[0], s1 = s[1], s2 = s[2], s3 = s[3];
    float* zp = g_z + r * BATCH;
    red_add_v4(zp + 0,  v * s0.x, v * s0.y, v * s0.z, v * s0.w);
    red_add_v4(zp + 4,  v * s1.x, v * s1.y, v * s1.z, v * s1.w);
    red_add_v4(zp + 8,  v * s2.x, v * s2.y, v * s2.z, v * s2.w);
    red_add_v4(zp + 12, v * s3.x, v * s3.y, v * s3.z, v * s3.w);
}

// ---------------------------------------------------------------------------
// Kernel 3: coarse partition by row-block (r>>5) — R11's proven version.
__global__ void __launch_bounds__(1024) k_coarse(const float* __restrict__ vals,
                                                 const int*   __restrict__ rows,
                                                 const int*   __restrict__ cols,
                                                 int nnz, int csz) {
    extern __shared__ float2 sbuf[];             // NCB * DEPTH_C
    __shared__ unsigned scnt[NCB];
    __shared__ unsigned sbase[NCB];
    int tid  = threadIdx.x;
    int w    = tid >> 5;
    int lane = tid & 31;
    int start = blockIdx.x * csz;
    int end   = min(nnz, start + csz);

    for (int base = start; base < end; base += TC) {
        if (tid < NCB) scnt[tid] = 0;
        __syncthreads();

        int i0 = base + tid * 8;
        if (base + TC <= end) {
            float4 v0 = *(const float4*)(vals + i0);
            float4 v1 = *(const float4*)(vals + i0 + 4);
            int4   r0 = *(const int4*)(rows + i0);
            int4   r1 = *(const int4*)(rows + i0 + 4);
            int4   c0 = *(const int4*)(cols + i0);
            int4   c1 = *(const int4*)(cols + i0 + 4);
            float vv[8] = {v0.x, v0.y, v0.z, v0.w, v1.x, v1.y, v1.z, v1.w};
            int   rr[8] = {r0.x, r0.y, r0.z, r0.w, r1.x, r1.y, r1.z, r1.w};
            int   cc[8] = {c0.x, c0.y, c0.z, c0.w, c1.x, c1.y, c1.z, c1.w};
#pragma unroll
            for (int k = 0; k < 8; k++) {
                int bin = rr[k] >> 5;
                unsigned pos = atomicAdd(&scnt[bin], 1u);
                float2 e = make_float2(vv[k],
                    __int_as_float(cc[k] | ((rr[k] & 31) << 13)));
                if (pos < DEPTH_C) sbuf[bin * DEPTH_C + pos] = e;
                else {                                   // ~never
                    unsigned p = atomicAdd(&g_ccur[bin], 1u);
                    if (p < CCAP) g_cbucket[(size_t)bin * CCAP + p] = e;
                }
            }
        } else {
            for (int k = 0; k < 8; k++) {
                int i = i0 + k;
                if (i < end) {
                    int r = rows[i], c = cols[i];
                    int bin = r >> 5;
                    unsigned pos = atomicAdd(&scnt[bin], 1u);
                    float2 e = make_float2(vals[i],
                        __int_as_float(c | ((r & 31) << 13)));
                    if (pos < DEPTH_C) sbuf[bin * DEPTH_C + pos] = e;
                    else {
                        unsigned p = atomicAdd(&g_ccur[bin], 1u);
                        if (p < CCAP) g_cbucket[(size_t)bin * CCAP + p] = e;
                    }
                }
            }
        }
        __syncthreads();

        if (tid < NCB) {
            unsigned c = min(scnt[tid], (unsigned)DEPTH_C);
            sbase[tid] = c ? atomicAdd(&g_ccur[tid], c) : 0u;
        }
        __syncthreads();

        for (int b = w * 8; b < w * 8 + 8; b++) {
            unsigned cnt = min(scnt[b], (unsigned)DEPTH_C);
            if (cnt == 0) continue;
            size_t dst = (size_t)b * CCAP + sbase[b];
            if (lane < cnt)
                g_cbucket[dst + lane] = sbuf[b * DEPTH_C + lane];
            if (cnt > 32 && lane + 32 < cnt)
                g_cbucket[dst + lane + 32] = sbuf[b * DEPTH_C + lane + 32];
        }
        __syncthreads();
    }
}

// ---------------------------------------------------------------------------
// Slow path for staging overflow (exact, ~never taken).
__device__ __forceinline__ void stage_overflow(float2 e, int cb, int rl) {
    int c = __float_as_int(e.y) & 8191;
    float v = e.x;
    const float4* s4 = reinterpret_cast<const float4*>(g_state_T + c * BATCH);
    float4 s0 = s4[0], s1 = s4[1], s2 = s4[2], s3 = s4[3];
    float* zp = g_z + ((cb << 5) | rl) * BATCH;
    red_add_v4(zp + 0,  v * s0.x, v * s0.y, v * s0.z, v * s0.w);
    red_add_v4(zp + 4,  v * s1.x, v * s1.y, v * s1.z, v * s1.w);
    red_add_v4(zp + 8,  v * s2.x, v * s2.y, v * s2.z, v * s2.w);
    red_add_v4(zp + 12, v * s3.x, v * s3.y, v * s3.z, v * s3.w);
}

// ---------------------------------------------------------------------------
// Kernel 4 (ncu slot): fused refine + gather + epilogue (R13 structure).
// Smaller staging (28KB) -> ~114KB L1D caches state_T; stream reads use
// ld.global.cs so they don't evict state lines.
__global__ void __launch_bounds__(512, 4) k_fuse(float* __restrict__ out) {
    extern __shared__ float2 stg[];              // 32 * DEPTH_F
    __shared__ unsigned scnt[32];
    __shared__ unsigned sdone;
    int tid  = threadIdx.x;
    int w    = tid >> 5;
    int lane = tid & 31;
    int half = lane >> 4;
    int b    = lane & 15;
    int cb   = blockIdx.x >> 1;
    int seg  = blockIdx.x & 1;

    int cnt = min(g_ccur[cb], (unsigned)CCAP);
    int s_beg = seg ? (cnt >> 1) : 0;
    int s_end = seg ? cnt : (cnt >> 1);
    const float2* __restrict__ src = g_cbucket + (size_t)cb * CCAP;

    float acc0 = 0.0f, acc1 = 0.0f;              // rows cb*32+2w, +2w+1

    for (int base = s_beg; base < s_end; base += TF) {
        if (tid < 32) scnt[tid] = 0;
        __syncthreads();

        int n = min(TF, s_end - base);
        // Stage: all 512 threads, plain per-thread smem atomics (proven).
        for (int k = tid; k < n; k += 512) {
            float2 e = ldcs_f2(src + base + k);  // streaming: don't pollute L1
            int rl = (__float_as_int(e.y) >> 13) & 31;
            unsigned pos = atomicAdd(&scnt[rl], 1u);
            if (pos < DEPTH_F) stg[rl * DEPTH_F + pos] = e;
            else               stage_overflow(e, cb, rl);
        }
        __syncthreads();

        // Drain: warp w -> rows 2w, 2w+1; half-warp = one entry; 8 in flight.
#pragma unroll
        for (int rr = 0; rr < 2; rr++) {
            int rl = (w << 1) | rr;
            int m = min(scnt[rl], (unsigned)DEPTH_F);
            const float2* row = stg + rl * DEPTH_F;
            float acc = 0.0f;
            int j = half;
            for (; j + 14 < m; j += 16) {
                float2 e0 = row[j];
                float2 e1 = row[j + 2];
                float2 e2 = row[j + 4];
                float2 e3 = row[j + 6];
                float2 e4 = row[j + 8];
                float2 e5 = row[j + 10];
                float2 e6 = row[j + 12];
                float2 e7 = row[j + 14];
                float s0 = g_state_T[(__float_as_int(e0.y) & 8191) * BATCH + b];
                float s1 = g_state_T[(__float_as_int(e1.y) & 8191) * BATCH + b];
                float s2 = g_state_T[(__float_as_int(e2.y) & 8191) * BATCH + b];
                float s3 = g_state_T[(__float_as_int(e3.y) & 8191) * BATCH + b];
                float s4 = g_state_T[(__float_as_int(e4.y) & 8191) * BATCH + b];
                float s5 = g_state_T[(__float_as_int(e5.y) & 8191) * BATCH + b];
                float s6 = g_state_T[(__float_as_int(e6.y) & 8191) * BATCH + b];
                float s7 = g_state_T[(__float_as_int(e7.y) & 8191) * BATCH + b];
                acc = fmaf(e0.x, s0, acc);
                acc = fmaf(e1.x, s1, acc);
                acc = fmaf(e2.x, s2, acc);
                acc = fmaf(e3.x, s3, acc);
                acc = fmaf(e4.x, s4, acc);
                acc = fmaf(e5.x, s5, acc);
                acc = fmaf(e6.x, s6, acc);
                acc = fmaf(e7.x, s7, acc);
            }
            for (; j < m; j += 2) {
                float2 e = row[j];
                acc = fmaf(e.x, g_state_T[(__float_as_int(e.y) & 8191) * BATCH + b], acc);
            }
            if (rr) acc1 += acc; else acc0 += acc;
        }
        __syncthreads();
    }

    // Flush 32-row partials into g_z.
    acc0 += __shfl_xor_sync(0xffffffffu, acc0, 16);
    acc1 += __shfl_xor_sync(0xffffffffu, acc1, 16);
    if (lane < BATCH) {
        int r0 = (cb << 5) | (w << 1);
        red_add_f32(g_z + r0 * BATCH + lane, acc0);
        red_add_f32(g_z + (r0 + 1) * BATCH + lane, acc1);
    }
    __syncthreads();

    // Completion counter: last segment-block of the bin runs the epilogue.
    if (tid == 0) {
        __threadfence();
        sdone = atomicAdd(&g_done[cb], 1u);
    }
    __syncthreads();
    if (sdone == NSEG - 1) {
        __threadfence();
        int i = (cb << 9) | tid;                 // bin's 512 outputs (32 rows x 16)
        float z = g_z[i];
        float s = g_state_T[i];                  // = state[b][r]
        int r = i >> 4;
        int bb = i & 15;
        out[bb * N_RES + r] = (1.0f - LEAK) * s + LEAK * erff(z);
    }
}

// ---------------------------------------------------------------------------
extern "C" void kernel_launch(void* const* d_in, const int* in_sizes, int n_in,
                              void* d_out, int out_size) {
    const float* state    = (const float*)d_in[0];
    const float* x        = (const float*)d_in[1];
    const float* res_vals = (const float*)d_in[2];
    const int*   res_rows = (const int*)  d_in[3];
    const int*   res_cols = (const int*)  d_in[4];
    const float* res_bias = (const float*)d_in[5];
    const float* in_vals  = (const float*)d_in[6];
    const int*   in_rows  = (const int*)  d_in[7];
    const int*   in_cols  = (const int*)  d_in[8];
    const float* in_bias  = (const float*)d_in[9];
    float* out = (float*)d_out;

    int res_nnz = in_sizes[2];
    int in_nnz  = in_sizes[6];
    int csz = ((res_nnz + NCH - 1) / NCH + 7) & ~7;

    static int smem_set = 0;
    if (!smem_set) {
        cudaFuncSetAttribute(k_coarse, cudaFuncAttributeMaxDynamicSharedMemorySize, COARSE_SMEM);
        cudaFuncSetAttribute(k_fuse,   cudaFuncAttributeMaxDynamicSharedMemorySize, FUSE_SMEM);
        smem_set = 1;
    }

    // Launch order: slot 4 (ncu capture) = k_fuse.
    k_init<<<(N_RES * BATCH + 255) / 256, 256>>>(state, x, res_bias, in_bias);

    k_in_spmm<<<(in_nnz + 255) / 256, 256>>>(in_vals, in_rows, in_cols, in_nnz);

    k_coarse<<<NCH, 1024, COARSE_SMEM>>>(res_vals, res_rows, res_cols, res_nnz, csz);

    k_fuse<<<NCB * NSEG, 512, FUSE_SMEM>>>(out);
}